// round 1
// baseline (speedup 1.0000x reference)
#include <cuda_runtime.h>
#include <math.h>

// Problem constants
#define BATCH 512
#define P 1152
#define NCAPS 10
#define T 16
#define D 8
#define PD (P*D)        // 9216
#define NT (NCAPS*T)    // 160
#define KCH 18          // split-K chunks for gemm1 (9216/18 = 512)
#define KPERCH (PD/KCH) // 512

// Scratch (device globals: no allocation allowed)
__device__ float g_Wt[PD*NT];           // Wt[pd][nt] = W[p,n,t,d]
__device__ float g_M[PD*NT];            // c-scaled Wt (per iteration)
__device__ float g_G[PD*NT];            // (1/B) X^T V
__device__ float g_spart[KCH*BATCH*NT]; // split-K partials of s
__device__ float g_s[BATCH*NT];
__device__ float g_v[BATCH*NT];
__device__ float g_b[P*NCAPS];          // routing logits (batch-invariant)
__device__ float g_c[P*NCAPS];          // coupling coefficients

// ---------------------------------------------------------------------------
// Prep: transpose W into [pd][nt] layout; init b=0, c=1/N
// ---------------------------------------------------------------------------
__global__ void k_prep(const float* __restrict__ W) {
    int i = blockIdx.x * blockDim.x + threadIdx.x;
    if (i < PD*NT) {
        int pd = i / NT, nt = i - pd*NT;
        int p = pd >> 3, d = pd & 7;
        int n = nt >> 4, t = nt & 15;
        g_Wt[i] = W[((p*NCAPS + n)*T + t)*D + d];
    }
    if (i < P*NCAPS) { g_b[i] = 0.0f; g_c[i] = 0.1f; }
}

// ---------------------------------------------------------------------------
// M = c (.) Wt   (fold coupling coefficients into the GEMM B-operand)
// ---------------------------------------------------------------------------
__global__ void k_scaleM() {
    int i = blockIdx.x * blockDim.x + threadIdx.x;
    if (i >= PD*NT) return;
    int pd = i / NT;
    int nt = i - pd*NT;
    int p = pd >> 3;
    int n = nt >> 4;
    g_M[i] = g_c[p*NCAPS + n] * g_Wt[i];
}

// ---------------------------------------------------------------------------
// GEMM1: spart[chunk][b][nt] = sum_{k in chunk} X[b][k] * M[k][nt]
// block: 64 b-rows x 160 nt-cols, K-chunk = 512. grid = (8, 18) = 144 blocks.
// ---------------------------------------------------------------------------
__global__ void __launch_bounds__(256) k_gemm1(const float* __restrict__ X) {
    __shared__ float Xs[64][20];     // padded stride to dodge STS conflicts
    __shared__ float Ms[16*NT];      // 16 x 160, flat

    int tid = threadIdx.x;
    int ty = tid >> 4, tx = tid & 15;
    int b0 = blockIdx.x * 64;
    int kc = blockIdx.y * KPERCH;

    float acc[4][10];
    #pragma unroll
    for (int i2 = 0; i2 < 4; ++i2)
        #pragma unroll
        for (int j = 0; j < 10; ++j) acc[i2][j] = 0.0f;

    int lr = tid >> 2;            // 0..63  (row in X tile)
    int lk = (tid & 3) * 4;       // 0,4,8,12

    for (int ks = 0; ks < KPERCH; ks += 16) {
        // Load X tile 64x16 (float4, coalesced)
        float4 xv = *(const float4*)&X[(size_t)(b0 + lr)*PD + kc + ks + lk];
        *(float4*)&Xs[lr][lk] = xv;
        // Load M tile 16x160 flat (fully coalesced scalar)
        const float* msrc = &g_M[(size_t)(kc + ks)*NT];
        #pragma unroll
        for (int u = 0; u < 10; ++u)
            Ms[tid + 256*u] = msrc[tid + 256*u];
        __syncthreads();

        #pragma unroll
        for (int kk = 0; kk < 16; ++kk) {
            float a0 = Xs[ty*4 + 0][kk];
            float a1 = Xs[ty*4 + 1][kk];
            float a2 = Xs[ty*4 + 2][kk];
            float a3 = Xs[ty*4 + 3][kk];
            #pragma unroll
            for (int j = 0; j < 10; ++j) {
                float bv = Ms[kk*NT + tx + 16*j];
                acc[0][j] += a0*bv;
                acc[1][j] += a1*bv;
                acc[2][j] += a2*bv;
                acc[3][j] += a3*bv;
            }
        }
        __syncthreads();
    }

    float* out = &g_spart[(size_t)blockIdx.y * BATCH * NT];
    #pragma unroll
    for (int i2 = 0; i2 < 4; ++i2)
        #pragma unroll
        for (int j = 0; j < 10; ++j)
            out[(size_t)(b0 + ty*4 + i2)*NT + tx + 16*j] = acc[i2][j];
}

// ---------------------------------------------------------------------------
// Reduce split-K partials: s = sum_ch spart[ch]
// ---------------------------------------------------------------------------
__global__ void k_reduceS() {
    int i = blockIdx.x * blockDim.x + threadIdx.x;
    if (i >= BATCH*NT) return;
    float a = 0.0f;
    #pragma unroll
    for (int ch = 0; ch < KCH; ++ch)
        a += g_spart[(size_t)ch*BATCH*NT + i];
    g_s[i] = a;
}

// ---------------------------------------------------------------------------
// squash: per (b,n): sq = sum_t s^2; v = sq*s / (1 + sq*(sqrt(sq)+1e-9))
// ---------------------------------------------------------------------------
__global__ void k_squash(float* __restrict__ out, int to_out) {
    int i = blockIdx.x * blockDim.x + threadIdx.x;   // b*NCAPS + n
    if (i >= BATCH*NCAPS) return;
    int b = i / NCAPS, n = i - b*NCAPS;
    const float* sp = &g_s[(size_t)b*NT + n*T];
    float sv[T];
    float sq = 0.0f;
    #pragma unroll
    for (int t = 0; t < T; ++t) { sv[t] = sp[t]; sq += sv[t]*sv[t]; }
    float nrm = sqrtf(sq);
    float f = sq / (1.0f + sq*(nrm + 1e-9f));
    float* dp = (to_out ? out : g_v) + (size_t)b*NT + n*T;
    #pragma unroll
    for (int t = 0; t < T; ++t) dp[t] = f*sv[t];
}

// ---------------------------------------------------------------------------
// GEMM2: G[pd][nt] = (1/B) * sum_b X[b][pd] * V[b][nt]
// block: 64 pd-rows x 160 nt-cols, full K=512. grid = 144 blocks.
// ---------------------------------------------------------------------------
__global__ void __launch_bounds__(256) k_gemm2(const float* __restrict__ X) {
    __shared__ float Xts[16][68];   // [b-k][pd-row], padded
    __shared__ float Vs[16*NT];

    int tid = threadIdx.x;
    int ty = tid >> 4, tx = tid & 15;
    int pd0 = blockIdx.x * 64;

    float acc[4][10];
    #pragma unroll
    for (int i2 = 0; i2 < 4; ++i2)
        #pragma unroll
        for (int j = 0; j < 10; ++j) acc[i2][j] = 0.0f;

    int lk = tid >> 4;            // 0..15 (b row within tile)
    int lr = (tid & 15) * 4;      // 0..60

    for (int bs = 0; bs < BATCH; bs += 16) {
        float4 xv = *(const float4*)&X[(size_t)(bs + lk)*PD + pd0 + lr];
        *(float4*)&Xts[lk][lr] = xv;
        const float* vsrc = &g_v[(size_t)bs*NT];
        #pragma unroll
        for (int u = 0; u < 10; ++u)
            Vs[tid + 256*u] = vsrc[tid + 256*u];
        __syncthreads();

        #pragma unroll
        for (int kk = 0; kk < 16; ++kk) {
            float a0 = Xts[kk][ty*4 + 0];
            float a1 = Xts[kk][ty*4 + 1];
            float a2 = Xts[kk][ty*4 + 2];
            float a3 = Xts[kk][ty*4 + 3];
            #pragma unroll
            for (int j = 0; j < 10; ++j) {
                float bv = Vs[kk*NT + tx + 16*j];
                acc[0][j] += a0*bv;
                acc[1][j] += a1*bv;
                acc[2][j] += a2*bv;
                acc[3][j] += a3*bv;
            }
        }
        __syncthreads();
    }

    const float inv = 1.0f / (float)BATCH;
    #pragma unroll
    for (int i2 = 0; i2 < 4; ++i2)
        #pragma unroll
        for (int j = 0; j < 10; ++j)
            g_G[(size_t)(pd0 + ty*4 + i2)*NT + tx + 16*j] = acc[i2][j]*inv;
}

// ---------------------------------------------------------------------------
// Routing update: bbar[p,n] = sum_{d,t} Wt[pd][nt]*G[pd][nt] (8x16 block),
// b += bbar, c = softmax_n(b). One block (160 threads) per p.
// ---------------------------------------------------------------------------
__global__ void k_route() {
    int p = blockIdx.x;
    int tid = threadIdx.x;            // 0..159 = n*16 + t
    int n = tid >> 4, t = tid & 15;
    __shared__ float sm[NT];
    __shared__ float bn[NCAPS];

    int base = (p*D)*NT + n*T + t;
    float a = 0.0f;
    #pragma unroll
    for (int d = 0; d < D; ++d)
        a += g_Wt[base + d*NT] * g_G[base + d*NT];
    sm[tid] = a;
    __syncthreads();

    if (t == 0) {
        float s = 0.0f;
        #pragma unroll
        for (int u = 0; u < T; ++u) s += sm[n*T + u];
        float bnew = g_b[p*NCAPS + n] + s;
        g_b[p*NCAPS + n] = bnew;
        bn[n] = bnew;
    }
    __syncthreads();

    if (tid == 0) {
        float mx = bn[0];
        #pragma unroll
        for (int u = 1; u < NCAPS; ++u) mx = fmaxf(mx, bn[u]);
        float es[NCAPS];
        float sum = 0.0f;
        #pragma unroll
        for (int u = 0; u < NCAPS; ++u) { es[u] = expf(bn[u] - mx); sum += es[u]; }
        float rs = 1.0f / sum;
        #pragma unroll
        for (int u = 0; u < NCAPS; ++u) g_c[p*NCAPS + u] = es[u]*rs;
    }
}

// ---------------------------------------------------------------------------
// Launch sequence (graph-capturable, default stream, no allocs, no syncs)
// ---------------------------------------------------------------------------
extern "C" void kernel_launch(void* const* d_in, const int* in_sizes, int n_in,
                              void* d_out, int out_size) {
    (void)in_sizes; (void)n_in; (void)out_size;
    const float* x = (const float*)d_in[0];   // [512, 1152, 8]
    const float* W = (const float*)d_in[1];   // [1152, 10, 16, 8]
    float* out = (float*)d_out;               // [512, 10, 16, 1]

    k_prep<<<(PD*NT + 255)/256, 256>>>(W);

    for (int it = 0; it < 3; ++it) {
        k_scaleM<<<(PD*NT + 255)/256, 256>>>();
        dim3 g1(BATCH/64, KCH);
        k_gemm1<<<g1, 256>>>(x);
        k_reduceS<<<(BATCH*NT + 255)/256, 256>>>();
        k_squash<<<(BATCH*NCAPS + 255)/256, 256>>>(out, it == 2 ? 1 : 0);
        if (it < 2) {
            k_gemm2<<<PD/64, 256>>>(x);
            k_route<<<P, 160>>>();
        }
    }
}

// round 3
// speedup vs baseline: 1.9738x; 1.9738x over previous
#include <cuda_runtime.h>
#include <cuda_fp16.h>
#include <math.h>
#include <stdint.h>

#define BATCH 512
#define P 1152
#define NCAPS 10
#define T 16
#define D 8
#define PD 9216          // P*D
#define NT 160           // NCAPS*T
#define KCH1 36          // split-K chunks gemm1 (36*256 = 9216)
#define KCH2 2           // split-K chunks gemm2 (2*256 = 512)

// SMEM tile geometry: K-stage 32, padded row stride 36 halves (72B, conflict-free frags)
#define SA 36
#define A_HALF_BYTES (128*SA*2)   // 9216
#define B_HALF_BYTES (160*SA*2)   // 11520
#define BUF_BYTES (2*A_HALF_BYTES + 2*B_HALF_BYTES)  // 41472
#define SMEM_BYTES (2*BUF_BYTES)                      // 82944

// ---------------- scratch (device globals) ----------------------------------
__device__ float g_Wt[NT*PD];        // Wt[nt][pd]  (B-operand of gemm1, k-contig)
__device__ float g_Wt2[PD*NT];       // Wt2[pd][nt] (for route)
__device__ float g_Xt[PD*BATCH];     // Xt[pd][b]   (A-operand of gemm2)
__device__ float g_spart[KCH1*BATCH*NT]; // gemm1 partials [ch][b][nt]
__device__ float g_s[BATCH*NT];      // s[b][nt]
__device__ float g_v[BATCH*NT];      // v[b][nt]
__device__ float g_Gp[KCH2*PD*NT];   // gemm2 partials [ch][pd][nt]
__device__ float g_b[P*NCAPS];
__device__ float g_c[P*NCAPS];

// ---------------- helpers ----------------------------------------------------
__device__ __forceinline__ void mma16816(float* c,
    uint32_t a0, uint32_t a1, uint32_t a2, uint32_t a3,
    uint32_t b0, uint32_t b1) {
    asm volatile(
        "mma.sync.aligned.m16n8k16.row.col.f32.f16.f16.f32 "
        "{%0,%1,%2,%3}, {%4,%5,%6,%7}, {%8,%9}, {%0,%1,%2,%3};"
        : "+f"(c[0]), "+f"(c[1]), "+f"(c[2]), "+f"(c[3])
        : "r"(a0), "r"(a1), "r"(a2), "r"(a3), "r"(b0), "r"(b1));
}

// split a float4 into hi/lo half2 pairs and store 8B each
__device__ __forceinline__ void sts_split(__half* hi, __half* lo, int off, float4 v) {
    float hx = __half2float(__float2half_rn(v.x));
    float hy = __half2float(__float2half_rn(v.y));
    float hz = __half2float(__float2half_rn(v.z));
    float hw = __half2float(__float2half_rn(v.w));
    *(__half2*)(hi + off)     = __floats2half2_rn(hx, hy);
    *(__half2*)(hi + off + 2) = __floats2half2_rn(hz, hw);
    *(__half2*)(lo + off)     = __floats2half2_rn(v.x - hx, v.y - hy);
    *(__half2*)(lo + off + 2) = __floats2half2_rn(v.z - hz, v.w - hw);
}

// ---------------- prep kernels -----------------------------------------------
__global__ void k_prep(const float* __restrict__ W) {
    int i = blockIdx.x * blockDim.x + threadIdx.x;
    if (i < NT*PD) {
        int nt = i / PD, pd = i - nt*PD;
        int p = pd >> 3, d = pd & 7, n = nt >> 4, t = nt & 15;
        float w = W[((p*NCAPS + n)*T + t)*D + d];
        g_Wt[i] = w;
        g_Wt2[(size_t)pd*NT + nt] = w;
    }
    if (i < P*NCAPS) { g_b[i] = 0.0f; g_c[i] = 0.1f; }
}

__global__ void k_transX(const float* __restrict__ X) {
    __shared__ float tb[32][33];
    int pd0 = blockIdx.x * 32, b0 = blockIdx.y * 32;
    int tx = threadIdx.x & 31, ty = threadIdx.x >> 5;  // ty 0..7
    #pragma unroll
    for (int j = 0; j < 32; j += 8)
        tb[ty + j][tx] = X[(size_t)(b0 + ty + j)*PD + pd0 + tx];
    __syncthreads();
    #pragma unroll
    for (int j = 0; j < 32; j += 8)
        g_Xt[(size_t)(pd0 + ty + j)*BATCH + b0 + tx] = tb[tx][ty + j];
}

// ---------------- GEMM mainloop shared pieces --------------------------------
// SMEM buffer layout per double-buffer: [Ahi][Alo][Bhi][Blo]
#define P_AHI(buf) ((__half*)(smem + (buf)*BUF_BYTES))
#define P_ALO(buf) ((__half*)(smem + (buf)*BUF_BYTES + A_HALF_BYTES))
#define P_BHI(buf) ((__half*)(smem + (buf)*BUF_BYTES + 2*A_HALF_BYTES))
#define P_BLO(buf) ((__half*)(smem + (buf)*BUF_BYTES + 2*A_HALF_BYTES + B_HALF_BYTES))

#define COMPUTE_STAGE(buf)                                                     \
    {                                                                          \
        const __half* Ah = P_AHI(buf); const __half* Al = P_ALO(buf);          \
        const __half* Bh = P_BHI(buf); const __half* Bl = P_BLO(buf);          \
        _Pragma("unroll")                                                      \
        for (int ko = 0; ko < 32; ko += 16) {                                  \
            uint32_t bh[5][2], bl[5][2];                                       \
            _Pragma("unroll")                                                  \
            for (int bt = 0; bt < 5; ++bt) {                                   \
                const __half* br = Bh + (wn40 + bt*8 + g)*SA + ko + qq;        \
                bh[bt][0] = *(const uint32_t*)br;                              \
                bh[bt][1] = *(const uint32_t*)(br + 8);                        \
                const __half* br2 = Bl + (wn40 + bt*8 + g)*SA + ko + qq;       \
                bl[bt][0] = *(const uint32_t*)br2;                             \
                bl[bt][1] = *(const uint32_t*)(br2 + 8);                       \
            }                                                                  \
            _Pragma("unroll")                                                  \
            for (int mt = 0; mt < 4; ++mt) {                                   \
                const __half* ar = Ah + (wm64 + mt*16 + g)*SA + ko + qq;       \
                uint32_t a0 = *(const uint32_t*)ar;                            \
                uint32_t a1 = *(const uint32_t*)(ar + 8*SA);                   \
                uint32_t a2 = *(const uint32_t*)(ar + 8);                      \
                uint32_t a3 = *(const uint32_t*)(ar + 8*SA + 8);               \
                const __half* ar2 = Al + (wm64 + mt*16 + g)*SA + ko + qq;      \
                uint32_t l0 = *(const uint32_t*)ar2;                           \
                uint32_t l1 = *(const uint32_t*)(ar2 + 8*SA);                  \
                uint32_t l2 = *(const uint32_t*)(ar2 + 8);                     \
                uint32_t l3 = *(const uint32_t*)(ar2 + 8*SA + 8);              \
                _Pragma("unroll")                                              \
                for (int bt = 0; bt < 5; ++bt) {                               \
                    mma16816(acc[mt][bt], a0, a1, a2, a3, bh[bt][0], bh[bt][1]);\
                    mma16816(acc[mt][bt], a0, a1, a2, a3, bl[bt][0], bl[bt][1]);\
                    mma16816(acc[mt][bt], l0, l1, l2, l3, bh[bt][0], bh[bt][1]);\
                }                                                              \
            }                                                                  \
        }                                                                      \
    }

// ---------------- GEMM1: spart[ch] = X[128b x 256k] * (c.Wt)[256k x 160] -----
__global__ void __launch_bounds__(256) k_gemm1(const float* __restrict__ X) {
    extern __shared__ char smem[];
    int tid = threadIdx.x;
    int wid = tid >> 5, lane = tid & 31;
    int wm64 = (wid >> 2) * 64;       // warp M offset (0 / 64)
    int wn40 = (wid & 3) * 40;        // warp N offset (0/40/80/120)
    int g = lane >> 2, qq = (lane & 3) * 2;
    int b0 = blockIdx.x * 128;
    int kc = blockIdx.y * 256;

    float acc[4][5][4];
    #pragma unroll
    for (int i = 0; i < 4; ++i)
        #pragma unroll
        for (int j = 0; j < 5; ++j)
            #pragma unroll
            for (int r = 0; r < 4; ++r) acc[i][j][r] = 0.0f;

    float4 pa[4], pb[5];
    auto ldA = [&](int kb) {
        #pragma unroll
        for (int u = 0; u < 4; ++u) {
            int idx = tid + 256*u, row = idx >> 3, q = idx & 7;
            pa[u] = *(const float4*)(X + (size_t)(b0 + row)*PD + kb + q*4);
        }
    };
    auto ldB = [&](int kb) {
        #pragma unroll
        for (int u = 0; u < 5; ++u) {
            int idx = tid + 256*u, row = idx >> 3, q = idx & 7;
            int k = kb + q*4;
            float4 v = *(const float4*)(g_Wt + (size_t)row*PD + k);
            float c = g_c[(k >> 3)*NCAPS + (row >> 4)];
            v.x *= c; v.y *= c; v.z *= c; v.w *= c;
            pb[u] = v;
        }
    };
    auto sts = [&](int buf) {
        __half* Ah = P_AHI(buf); __half* Al = P_ALO(buf);
        __half* Bh = P_BHI(buf); __half* Bl = P_BLO(buf);
        #pragma unroll
        for (int u = 0; u < 4; ++u) {
            int idx = tid + 256*u, row = idx >> 3, q = idx & 7;
            sts_split(Ah, Al, row*SA + q*4, pa[u]);
        }
        #pragma unroll
        for (int u = 0; u < 5; ++u) {
            int idx = tid + 256*u, row = idx >> 3, q = idx & 7;
            sts_split(Bh, Bl, row*SA + q*4, pb[u]);
        }
    };

    ldA(kc); ldB(kc);
    sts(0);
    __syncthreads();

    for (int s = 0; s < 8; ++s) {
        int buf = s & 1;
        if (s < 7) { ldA(kc + (s+1)*32); ldB(kc + (s+1)*32); }
        COMPUTE_STAGE(buf);
        __syncthreads();
        if (s < 7) { sts(1 - buf); __syncthreads(); }
    }

    float* out = g_spart + (size_t)blockIdx.y * BATCH * NT;
    #pragma unroll
    for (int mt = 0; mt < 4; ++mt) {
        int row = b0 + wm64 + mt*16 + g;
        #pragma unroll
        for (int bt = 0; bt < 5; ++bt) {
            int col = wn40 + bt*8 + qq;
            *(float2*)&out[(size_t)row*NT + col]       = make_float2(acc[mt][bt][0], acc[mt][bt][1]);
            *(float2*)&out[(size_t)(row + 8)*NT + col] = make_float2(acc[mt][bt][2], acc[mt][bt][3]);
        }
    }
}

// ---------------- GEMM2: Gp[ch] = Xt[128pd x 256b] * V^T[256b x 160] ---------
__global__ void __launch_bounds__(256) k_gemm2() {
    extern __shared__ char smem[];
    int tid = threadIdx.x;
    int wid = tid >> 5, lane = tid & 31;
    int wm64 = (wid >> 2) * 64;
    int wn40 = (wid & 3) * 40;
    int g = lane >> 2, qq = (lane & 3) * 2;
    int pd0 = blockIdx.x * 128;
    int kc = blockIdx.y * 256;

    float acc[4][5][4];
    #pragma unroll
    for (int i = 0; i < 4; ++i)
        #pragma unroll
        for (int j = 0; j < 5; ++j)
            #pragma unroll
            for (int r = 0; r < 4; ++r) acc[i][j][r] = 0.0f;

    float4 pa[4], pb[5];
    auto ldA = [&](int kb) {
        #pragma unroll
        for (int u = 0; u < 4; ++u) {
            int idx = tid + 256*u, row = idx >> 3, q = idx & 7;
            pa[u] = *(const float4*)(g_Xt + (size_t)(pd0 + row)*BATCH + kb + q*4);
        }
    };
    // V is stored row-major [b][nt]; transpose into Bs[nt][k=b_local] during STS.
    auto ldB = [&](int kb) {
        #pragma unroll
        for (int u = 0; u < 5; ++u) {
            int idx = tid + 256*u;             // 0..1279 float4s
            int b = kb + idx/40, c4 = idx%40;
            pb[u] = *(const float4*)(g_v + (size_t)b*NT + c4*4);
        }
    };
    auto sts = [&](int buf) {
        __half* Ah = P_AHI(buf); __half* Al = P_ALO(buf);
        __half* Bh = P_BHI(buf); __half* Bl = P_BLO(buf);
        #pragma unroll
        for (int u = 0; u < 4; ++u) {
            int idx = tid + 256*u, row = idx >> 3, q = idx & 7;
            sts_split(Ah, Al, row*SA + q*4, pa[u]);
        }
        #pragma unroll
        for (int u = 0; u < 5; ++u) {
            int idx = tid + 256*u;
            int bl_ = idx/40 % 32, c4 = idx%40;   // b_local 0..31
            float vv[4] = {pb[u].x, pb[u].y, pb[u].z, pb[u].w};
            #pragma unroll
            for (int j = 0; j < 4; ++j) {
                int nt = c4*4 + j;
                float h = __half2float(__float2half_rn(vv[j]));
                Bh[nt*SA + bl_] = __float2half_rn(vv[j]);
                Bl[nt*SA + bl_] = __float2half_rn(vv[j] - h);
            }
        }
    };

    ldA(kc); ldB(kc);
    sts(0);
    __syncthreads();

    for (int s = 0; s < 8; ++s) {
        int buf = s & 1;
        if (s < 7) { ldA(kc + (s+1)*32); ldB(kc + (s+1)*32); }
        COMPUTE_STAGE(buf);
        __syncthreads();
        if (s < 7) { sts(1 - buf); __syncthreads(); }
    }

    const float inv = 1.0f / (float)BATCH;
    float* out = g_Gp + (size_t)blockIdx.y * PD * NT;
    #pragma unroll
    for (int mt = 0; mt < 4; ++mt) {
        int row = pd0 + wm64 + mt*16 + g;
        #pragma unroll
        for (int bt = 0; bt < 5; ++bt) {
            int col = wn40 + bt*8 + qq;
            *(float2*)&out[(size_t)row*NT + col]       = make_float2(acc[mt][bt][0]*inv, acc[mt][bt][1]*inv);
            *(float2*)&out[(size_t)(row + 8)*NT + col] = make_float2(acc[mt][bt][2]*inv, acc[mt][bt][3]*inv);
        }
    }
}

// ---------------- reduce split-K partials of s -------------------------------
__global__ void k_reduceS() {
    int i = blockIdx.x * blockDim.x + threadIdx.x;
    if (i >= BATCH*NT) return;
    float a = 0.0f;
    #pragma unroll
    for (int ch = 0; ch < KCH1; ++ch)
        a += g_spart[(size_t)ch*BATCH*NT + i];
    g_s[i] = a;
}

// ---------------- squash -----------------------------------------------------
__global__ void k_squash(float* __restrict__ out, int final_it) {
    int i = blockIdx.x * blockDim.x + threadIdx.x;   // b*NCAPS + n
    if (i >= BATCH*NCAPS) return;
    int b = i / NCAPS, n = i - b*NCAPS;
    const float* sp = &g_s[(size_t)b*NT + n*T];
    float sv[T];
    float sq = 0.0f;
    #pragma unroll
    for (int t = 0; t < T; ++t) { sv[t] = sp[t]; sq += sv[t]*sv[t]; }
    float nrm = sqrtf(sq);
    float f = sq / (1.0f + sq*(nrm + 1e-9f));
    float* dp = (final_it ? out : g_v) + (size_t)b*NT + n*T;
    #pragma unroll
    for (int t = 0; t < T; ++t) dp[t] = f*sv[t];
}

// ---------------- routing update ---------------------------------------------
__global__ void k_route() {
    int p = blockIdx.x;
    int tid = threadIdx.x;            // 0..159 = n*16 + t
    int n = tid >> 4, t = tid & 15;
    __shared__ float sm[NT];
    __shared__ float bn[NCAPS];

    size_t base = (size_t)(p*D)*NT + n*T + t;
    float a = 0.0f;
    #pragma unroll
    for (int d = 0; d < D; ++d) {
        float gg = g_Gp[base + d*NT] + g_Gp[(size_t)PD*NT + base + d*NT];
        a += g_Wt2[base + d*NT] * gg;
    }
    sm[tid] = a;
    __syncthreads();

    if (t == 0) {
        float s = 0.0f;
        #pragma unroll
        for (int u = 0; u < T; ++u) s += sm[n*T + u];
        float bnew = g_b[p*NCAPS + n] + s;
        g_b[p*NCAPS + n] = bnew;
        bn[n] = bnew;
    }
    __syncthreads();

    if (tid == 0) {
        float mx = bn[0];
        #pragma unroll
        for (int u = 1; u < NCAPS; ++u) mx = fmaxf(mx, bn[u]);
        float es[NCAPS];
        float sum = 0.0f;
        #pragma unroll
        for (int u = 0; u < NCAPS; ++u) { es[u] = expf(bn[u] - mx); sum += es[u]; }
        float rs = 1.0f / sum;
        #pragma unroll
        for (int u = 0; u < NCAPS; ++u) g_c[p*NCAPS + u] = es[u]*rs;
    }
}

// ---------------- launch -----------------------------------------------------
extern "C" void kernel_launch(void* const* d_in, const int* in_sizes, int n_in,
                              void* d_out, int out_size) {
    (void)in_sizes; (void)n_in; (void)out_size;
    const float* x = (const float*)d_in[0];   // [512, 1152, 8]
    const float* W = (const float*)d_in[1];   // [1152, 10, 16, 8]
    float* out = (float*)d_out;               // [512, 10, 16, 1]

    cudaFuncSetAttribute((const void*)k_gemm1,
                         cudaFuncAttributeMaxDynamicSharedMemorySize, SMEM_BYTES);
    cudaFuncSetAttribute((const void*)k_gemm2,
                         cudaFuncAttributeMaxDynamicSharedMemorySize, SMEM_BYTES);

    k_prep<<<(NT*PD + 255)/256, 256>>>(W);
    k_transX<<<dim3(PD/32, BATCH/32), 256>>>(x);

    for (int it = 0; it < 3; ++it) {
        k_gemm1<<<dim3(BATCH/128, KCH1), 256, SMEM_BYTES>>>(x);
        k_reduceS<<<(BATCH*NT + 255)/256, 256>>>();
        k_squash<<<(BATCH*NCAPS + 255)/256, 256>>>(out, it == 2 ? 1 : 0);
        if (it < 2) {
            k_gemm2<<<dim3(PD/128, KCH2), 256, SMEM_BYTES>>>();
            k_route<<<P, NT>>>();
        }
    }
}

// round 4
// speedup vs baseline: 1.9988x; 1.0127x over previous
#include <cuda_runtime.h>
#include <cuda_fp16.h>
#include <math.h>
#include <stdint.h>

#define BATCH 512
#define P 1152
#define NCAPS 10
#define T 16
#define D 8
#define PD 9216          // P*D
#define NT 160           // NCAPS*T
#define KCH1 36          // split-K chunks gemm1 (36*256 = 9216)
#define KCH2 2           // split-K chunks gemm2 (2*256 = 512)

// SMEM tile geometry: K-stage 32 halves, row stride 40 halves (80B: 16B-aligned
// for cp.async, 20-bank stride => conflict-free 8-row frag reads)
#define SA 40
#define ABYTES (128*SA*2)                 // 10240
#define BBYTES (160*SA*2)                 // 12800
#define BUF_BYTES (2*ABYTES + 2*BBYTES)   // 46080
#define SMEM_BYTES (2*BUF_BYTES)          // 92160

// ---------------- scratch (device globals) ----------------------------------
__device__ float  g_Wt[NT*PD];        // Wt[nt][pd] fp32 (source for splitB)
__device__ float  g_Wt2[PD*NT];       // Wt2[pd][nt] fp32 (gemm2 epilogue)
__device__ __half g_Xh[BATCH*PD];     // X hi  [b][pd]  (gemm1 A)
__device__ __half g_Xl[BATCH*PD];     // X lo
__device__ __half g_Xth[PD*BATCH];    // X^T hi [pd][b] (gemm2 A)
__device__ __half g_Xtl[PD*BATCH];
__device__ __half g_Bh[NT*PD];        // (c.W) hi [nt][pd] (gemm1 B, per iter)
__device__ __half g_Bl[NT*PD];
__device__ __half g_vh[NT*BATCH];     // v hi [nt][b] (gemm2 B)
__device__ __half g_vl[NT*BATCH];
__device__ float  g_spart[KCH1*BATCH*NT]; // gemm1 partials [ch][b][nt]
__device__ float  g_bbar[P*NCAPS];    // fused agreement accumulator
__device__ float  g_b[P*NCAPS];
__device__ float  g_c[P*NCAPS];

// ---------------- helpers ----------------------------------------------------
__device__ __forceinline__ void mma16816(float* c,
    uint32_t a0, uint32_t a1, uint32_t a2, uint32_t a3,
    uint32_t b0, uint32_t b1) {
    asm volatile(
        "mma.sync.aligned.m16n8k16.row.col.f32.f16.f16.f32 "
        "{%0,%1,%2,%3}, {%4,%5,%6,%7}, {%8,%9}, {%0,%1,%2,%3};"
        : "+f"(c[0]), "+f"(c[1]), "+f"(c[2]), "+f"(c[3])
        : "r"(a0), "r"(a1), "r"(a2), "r"(a3), "r"(b0), "r"(b1));
}
__device__ __forceinline__ uint32_t s2u(const void* p) {
    uint32_t a;
    asm("{ .reg .u64 t; cvta.to.shared.u64 t, %1; cvt.u32.u64 %0, t; }"
        : "=r"(a) : "l"(p));
    return a;
}
__device__ __forceinline__ void cpasync16(uint32_t dst, const void* src) {
    asm volatile("cp.async.cg.shared.global [%0], [%1], 16;"
        :: "r"(dst), "l"(__cvta_generic_to_global(src)));
}
#define CP_COMMIT() asm volatile("cp.async.commit_group;" ::: "memory")
#define CP_WAIT(n)  asm volatile("cp.async.wait_group %0;" :: "n"(n) : "memory")

// ---------------- prep: W layouts + b/c init ---------------------------------
__global__ void k_prep(const float* __restrict__ W) {
    int i = blockIdx.x * blockDim.x + threadIdx.x;
    if (i < NT*PD) {
        int nt = i / PD, pd = i - nt*PD;
        int p = pd >> 3, d = pd & 7, n = nt >> 4, t = nt & 15;
        float w = W[((p*NCAPS + n)*T + t)*D + d];
        g_Wt[i] = w;
        g_Wt2[(size_t)pd*NT + nt] = w;
    }
    if (i < P*NCAPS) { g_b[i] = 0.0f; g_c[i] = 0.1f; }
}

// ---------------- prep: split X into hi/lo, both layouts ---------------------
__global__ void k_prepX(const float* __restrict__ X) {
    __shared__ uint32_t tb[32][33];
    int pd0 = blockIdx.x * 32, b0 = blockIdx.y * 32;
    int tx = threadIdx.x & 31, ty = threadIdx.x >> 5;  // ty 0..7
    #pragma unroll
    for (int j = 0; j < 32; j += 8) {
        float v = X[(size_t)(b0 + ty + j)*PD + pd0 + tx];
        __half h = __float2half_rn(v);
        __half l = __float2half_rn(v - __half2float(h));
        g_Xh[(size_t)(b0 + ty + j)*PD + pd0 + tx] = h;
        g_Xl[(size_t)(b0 + ty + j)*PD + pd0 + tx] = l;
        __half2 hl = __halves2half2(h, l);
        tb[ty + j][tx] = *(uint32_t*)&hl;
    }
    __syncthreads();
    #pragma unroll
    for (int j = 0; j < 32; j += 8) {
        uint32_t u = tb[tx][ty + j];
        __half2 hl = *(__half2*)&u;
        g_Xth[(size_t)(pd0 + ty + j)*BATCH + b0 + tx] = __low2half(hl);
        g_Xtl[(size_t)(pd0 + ty + j)*BATCH + b0 + tx] = __high2half(hl);
    }
}

// ---------------- per-iter: B = split(c .* Wt) -------------------------------
__global__ void k_splitB() {
    int i4 = blockIdx.x * blockDim.x + threadIdx.x;   // handles 4 elems
    if (i4 >= NT*PD/4) return;
    size_t base = (size_t)i4 * 4;
    int nt = (int)(base / PD), pd = (int)(base - (size_t)nt*PD);
    float c = g_c[(pd >> 3)*NCAPS + (nt >> 4)];
    float4 w = *(const float4*)&g_Wt[base];
    w.x *= c; w.y *= c; w.z *= c; w.w *= c;
    __half hx = __float2half_rn(w.x), hy = __float2half_rn(w.y);
    __half hz = __float2half_rn(w.z), hw = __float2half_rn(w.w);
    *(__half2*)&g_Bh[base]     = __halves2half2(hx, hy);
    *(__half2*)&g_Bh[base + 2] = __halves2half2(hz, hw);
    *(__half2*)&g_Bl[base]     = __halves2half2(
        __float2half_rn(w.x - __half2float(hx)), __float2half_rn(w.y - __half2float(hy)));
    *(__half2*)&g_Bl[base + 2] = __halves2half2(
        __float2half_rn(w.z - __half2float(hz)), __float2half_rn(w.w - __half2float(hw)));
}

// ---------------- SMEM layout per double-buffer ------------------------------
#define P_AHI(buf) ((__half*)(smem + (buf)*BUF_BYTES))
#define P_ALO(buf) ((__half*)(smem + (buf)*BUF_BYTES + ABYTES))
#define P_BHI(buf) ((__half*)(smem + (buf)*BUF_BYTES + 2*ABYTES))
#define P_BLO(buf) ((__half*)(smem + (buf)*BUF_BYTES + 2*ABYTES + BBYTES))
#define O_AHI(buf) ((buf)*BUF_BYTES)
#define O_ALO(buf) ((buf)*BUF_BYTES + ABYTES)
#define O_BHI(buf) ((buf)*BUF_BYTES + 2*ABYTES)
#define O_BLO(buf) ((buf)*BUF_BYTES + 2*ABYTES + BBYTES)

#define COMPUTE_STAGE(buf)                                                     \
    {                                                                          \
        const __half* Ah = P_AHI(buf); const __half* Al = P_ALO(buf);          \
        const __half* Bh = P_BHI(buf); const __half* Bl = P_BLO(buf);          \
        _Pragma("unroll")                                                      \
        for (int ko = 0; ko < 32; ko += 16) {                                  \
            uint32_t bh[5][2], bl[5][2];                                       \
            _Pragma("unroll")                                                  \
            for (int bt = 0; bt < 5; ++bt) {                                   \
                const __half* br = Bh + (wn40 + bt*8 + g)*SA + ko + qq;        \
                bh[bt][0] = *(const uint32_t*)br;                              \
                bh[bt][1] = *(const uint32_t*)(br + 8);                        \
                const __half* br2 = Bl + (wn40 + bt*8 + g)*SA + ko + qq;       \
                bl[bt][0] = *(const uint32_t*)br2;                             \
                bl[bt][1] = *(const uint32_t*)(br2 + 8);                       \
            }                                                                  \
            _Pragma("unroll")                                                  \
            for (int mt = 0; mt < 4; ++mt) {                                   \
                const __half* ar = Ah + (wm64 + mt*16 + g)*SA + ko + qq;       \
                uint32_t a0 = *(const uint32_t*)ar;                            \
                uint32_t a1 = *(const uint32_t*)(ar + 8*SA);                   \
                uint32_t a2 = *(const uint32_t*)(ar + 8);                      \
                uint32_t a3 = *(const uint32_t*)(ar + 8*SA + 8);               \
                const __half* ar2 = Al + (wm64 + mt*16 + g)*SA + ko + qq;      \
                uint32_t l0 = *(const uint32_t*)ar2;                           \
                uint32_t l1 = *(const uint32_t*)(ar2 + 8*SA);                  \
                uint32_t l2 = *(const uint32_t*)(ar2 + 8);                     \
                uint32_t l3 = *(const uint32_t*)(ar2 + 8*SA + 8);              \
                _Pragma("unroll")                                              \
                for (int bt = 0; bt < 5; ++bt) {                               \
                    mma16816(acc[mt][bt], a0, a1, a2, a3, bh[bt][0], bh[bt][1]);\
                    mma16816(acc[mt][bt], a0, a1, a2, a3, bl[bt][0], bl[bt][1]);\
                    mma16816(acc[mt][bt], l0, l1, l2, l3, bh[bt][0], bh[bt][1]);\
                }                                                              \
            }                                                                  \
        }                                                                      \
    }

// ---------------- GEMM1: spart[ch] = Xsplit[128b x 256k] * Bsplit[256k x 160]
__global__ void __launch_bounds__(256) k_gemm1() {
    extern __shared__ char smem[];
    uint32_t sb = s2u(smem);
    int tid = threadIdx.x;
    int wid = tid >> 5, lane = tid & 31;
    int wm64 = (wid >> 2) * 64;
    int wn40 = (wid & 3) * 40;
    int g = lane >> 2, qq = (lane & 3) * 2;
    int b0 = blockIdx.x * 128;
    int kc = blockIdx.y * 256;

    float acc[4][5][4];
    #pragma unroll
    for (int i = 0; i < 4; ++i)
        #pragma unroll
        for (int j = 0; j < 5; ++j)
            #pragma unroll
            for (int r = 0; r < 4; ++r) acc[i][j][r] = 0.0f;

    auto issue = [&](int s, int buf) {
        int kb = kc + s*32;
        #pragma unroll
        for (int u = 0; u < 2; ++u) {
            int ch = tid*2 + u;                 // 0..511 (A: 128 rows x 4 chunks)
            int row = ch >> 2, q = ch & 3;
            cpasync16(sb + O_AHI(buf) + row*(SA*2) + q*16,
                      g_Xh + (size_t)(b0 + row)*PD + kb + q*8);
            cpasync16(sb + O_ALO(buf) + row*(SA*2) + q*16,
                      g_Xl + (size_t)(b0 + row)*PD + kb + q*8);
        }
        #pragma unroll
        for (int u = 0; u < 3; ++u) {
            int ch = tid + 256*u;               // 0..639 (B: 160 rows x 4 chunks)
            if (ch < 640) {
                int row = ch >> 2, q = ch & 3;
                cpasync16(sb + O_BHI(buf) + row*(SA*2) + q*16,
                          g_Bh + (size_t)row*PD + kb + q*8);
                cpasync16(sb + O_BLO(buf) + row*(SA*2) + q*16,
                          g_Bl + (size_t)row*PD + kb + q*8);
            }
        }
    };

    issue(0, 0); CP_COMMIT();
    for (int s = 0; s < 8; ++s) {
        if (s < 7) { issue(s + 1, (s + 1) & 1); CP_COMMIT(); CP_WAIT(1); }
        else       { CP_WAIT(0); }
        __syncthreads();
        COMPUTE_STAGE(s & 1);
        __syncthreads();
    }

    float* out = g_spart + (size_t)blockIdx.y * BATCH * NT;
    #pragma unroll
    for (int mt = 0; mt < 4; ++mt) {
        int row = b0 + wm64 + mt*16 + g;
        #pragma unroll
        for (int bt = 0; bt < 5; ++bt) {
            int col = wn40 + bt*8 + qq;
            *(float2*)&out[(size_t)row*NT + col]       = make_float2(acc[mt][bt][0], acc[mt][bt][1]);
            *(float2*)&out[(size_t)(row + 8)*NT + col] = make_float2(acc[mt][bt][2], acc[mt][bt][3]);
        }
    }
}

// ---------------- GEMM2 + fused agreement epilogue ---------------------------
// Gp-free: bbar[p][n] += (1/B) sum_{d,t in tile} W[pd][nt] * (Xt V)[pd][nt]
__global__ void __launch_bounds__(256) k_gemm2() {
    extern __shared__ char smem[];
    __shared__ float bb[16][12];
    uint32_t sb = s2u(smem);
    int tid = threadIdx.x;
    int wid = tid >> 5, lane = tid & 31;
    int wm64 = (wid >> 2) * 64;
    int wn40 = (wid & 3) * 40;
    int g = lane >> 2, qq = (lane & 3) * 2;
    int pd0 = blockIdx.x * 128;
    int kc = blockIdx.y * 256;

    if (tid < 160) bb[tid / 10][tid % 10] = 0.0f;

    float acc[4][5][4];
    #pragma unroll
    for (int i = 0; i < 4; ++i)
        #pragma unroll
        for (int j = 0; j < 5; ++j)
            #pragma unroll
            for (int r = 0; r < 4; ++r) acc[i][j][r] = 0.0f;

    auto issue = [&](int s, int buf) {
        int kb = kc + s*32;
        #pragma unroll
        for (int u = 0; u < 2; ++u) {
            int ch = tid*2 + u;
            int row = ch >> 2, q = ch & 3;
            cpasync16(sb + O_AHI(buf) + row*(SA*2) + q*16,
                      g_Xth + (size_t)(pd0 + row)*BATCH + kb + q*8);
            cpasync16(sb + O_ALO(buf) + row*(SA*2) + q*16,
                      g_Xtl + (size_t)(pd0 + row)*BATCH + kb + q*8);
        }
        #pragma unroll
        for (int u = 0; u < 3; ++u) {
            int ch = tid + 256*u;
            if (ch < 640) {
                int row = ch >> 2, q = ch & 3;
                cpasync16(sb + O_BHI(buf) + row*(SA*2) + q*16,
                          g_vh + (size_t)row*BATCH + kb + q*8);
                cpasync16(sb + O_BLO(buf) + row*(SA*2) + q*16,
                          g_vl + (size_t)row*BATCH + kb + q*8);
            }
        }
    };

    issue(0, 0); CP_COMMIT();
    for (int s = 0; s < 8; ++s) {
        if (s < 7) { issue(s + 1, (s + 1) & 1); CP_COMMIT(); CP_WAIT(1); }
        else       { CP_WAIT(0); }
        __syncthreads();
        COMPUTE_STAGE(s & 1);
        __syncthreads();
    }
    // bb[] zero-init is ordered before accumulation by the mainloop syncthreads

    // Fused agreement: per (mt,bt): dot acc with W, reduce over g-lanes, smem atomic
    #pragma unroll
    for (int mt = 0; mt < 4; ++mt) {
        int r0 = wm64 + mt*16 + g;
        int p0 = (wm64 + mt*16) >> 3;       // p_local of rows [.. , ..+8)
        #pragma unroll
        for (int bt = 0; bt < 5; ++bt) {
            int col = wn40 + bt*8 + qq;
            int n = col >> 4;
            float2 w0 = *(const float2*)&g_Wt2[(size_t)(pd0 + r0)*NT + col];
            float2 w1 = *(const float2*)&g_Wt2[(size_t)(pd0 + r0 + 8)*NT + col];
            float v0 = acc[mt][bt][0]*w0.x + acc[mt][bt][1]*w0.y;
            float v1 = acc[mt][bt][2]*w1.x + acc[mt][bt][3]*w1.y;
            #pragma unroll
            for (int o = 4; o < 32; o <<= 1) {
                v0 += __shfl_xor_sync(0xffffffffu, v0, o);
                v1 += __shfl_xor_sync(0xffffffffu, v1, o);
            }
            if (lane < 4) {
                atomicAdd(&bb[p0][n], v0);
                atomicAdd(&bb[p0 + 1][n], v1);
            }
        }
    }
    __syncthreads();
    if (tid < 160) {
        const float inv = 1.0f / (float)BATCH;
        atomicAdd(&g_bbar[(pd0/8 + tid/10)*NCAPS + tid % 10],
                  bb[tid / 10][tid % 10] * inv);
    }
}

// ---------------- fused reduce + squash (+ v split + bbar zero) --------------
__global__ void k_redsquash(float* __restrict__ out, int final_it) {
    int i = blockIdx.x * blockDim.x + threadIdx.x;   // [0, BATCH*NT)
    float s = 0.0f;
    #pragma unroll
    for (int ch = 0; ch < KCH1; ++ch)
        s += g_spart[(size_t)ch*BATCH*NT + i];
    float ss = s*s;
    #pragma unroll
    for (int o = 1; o < 16; o <<= 1)
        ss += __shfl_xor_sync(0xffffffffu, ss, o);   // 16-lane groups (aligned)
    float nrm = sqrtf(ss);
    float f = ss / (1.0f + ss*(nrm + 1e-9f));
    float v = f*s;
    if (final_it) {
        out[i] = v;
    } else {
        int b = i / NT, nt = i - b*NT;
        __half h = __float2half_rn(v);
        g_vh[(size_t)nt*BATCH + b] = h;
        g_vl[(size_t)nt*BATCH + b] = __float2half_rn(v - __half2float(h));
        if (i < P*NCAPS) g_bbar[i] = 0.0f;
    }
}

// ---------------- routing softmax --------------------------------------------
__global__ void k_route() {
    int p = blockIdx.x * blockDim.x + threadIdx.x;
    if (p >= P) return;
    float bn[NCAPS];
    float mx = -1e30f;
    #pragma unroll
    for (int n = 0; n < NCAPS; ++n) {
        bn[n] = g_b[p*NCAPS + n] + g_bbar[p*NCAPS + n];
        g_b[p*NCAPS + n] = bn[n];
        mx = fmaxf(mx, bn[n]);
    }
    float sum = 0.0f;
    #pragma unroll
    for (int n = 0; n < NCAPS; ++n) { bn[n] = expf(bn[n] - mx); sum += bn[n]; }
    float rs = 1.0f / sum;
    #pragma unroll
    for (int n = 0; n < NCAPS; ++n) g_c[p*NCAPS + n] = bn[n]*rs;
}

// ---------------- launch -----------------------------------------------------
extern "C" void kernel_launch(void* const* d_in, const int* in_sizes, int n_in,
                              void* d_out, int out_size) {
    (void)in_sizes; (void)n_in; (void)out_size;
    const float* x = (const float*)d_in[0];   // [512, 1152, 8]
    const float* W = (const float*)d_in[1];   // [1152, 10, 16, 8]
    float* out = (float*)d_out;               // [512, 10, 16, 1]

    cudaFuncSetAttribute((const void*)k_gemm1,
                         cudaFuncAttributeMaxDynamicSharedMemorySize, SMEM_BYTES);
    cudaFuncSetAttribute((const void*)k_gemm2,
                         cudaFuncAttributeMaxDynamicSharedMemorySize, SMEM_BYTES);

    k_prep<<<(NT*PD + 255)/256, 256>>>(W);
    k_prepX<<<dim3(PD/32, BATCH/32), 256>>>(x);

    for (int it = 0; it < 3; ++it) {
        k_splitB<<<(NT*PD/4 + 255)/256, 256>>>();
        k_gemm1<<<dim3(BATCH/128, KCH1), 256, SMEM_BYTES>>>();
        k_redsquash<<<(BATCH*NT)/256, 256>>>(out, it == 2 ? 1 : 0);
        if (it < 2) {
            k_gemm2<<<dim3(PD/128, KCH2), 256, SMEM_BYTES>>>();
            k_route<<<(P + 255)/256, 256>>>();
        }
    }
}

// round 5
// speedup vs baseline: 2.2509x; 1.1261x over previous
#include <cuda_runtime.h>
#include <cuda_fp16.h>
#include <math.h>
#include <stdint.h>

#define BATCH 512
#define P 1152
#define NCAPS 10
#define T 16
#define D 8
#define PD 9216          // P*D
#define NT 160           // NCAPS*T
#define KCH1 36          // split-K chunks gemm1 (36*256 = 9216)
#define KCH2 2           // split-K chunks gemm2 (2*256 = 512)

// SMEM stage: K=32 halves, row stride 40 halves (80B; 16B-aligned, 20-bank stride)
#define SA 40
#define ABYTES (128*SA*2)                 // 10240
#define BBYTES (160*SA*2)                 // 12800
#define BUF_BYTES (2*ABYTES + 2*BBYTES)   // 46080
#define NSTAGE 3
#define SMEM_BYTES (NSTAGE*BUF_BYTES)     // 138240

// ---------------- scratch ----------------------------------------------------
__device__ float  g_Wt[NT*PD];        // Wt[nt][pd] fp32
__device__ float  g_Wt2[PD*NT];       // Wt2[pd][nt] fp32 (gemm2 epilogue)
__device__ __half g_Xh[BATCH*PD];     // X hi [b][pd]
__device__ __half g_Xl[BATCH*PD];
__device__ __half g_Xth[PD*BATCH];    // X^T hi [pd][b]
__device__ __half g_Xtl[PD*BATCH];
__device__ __half g_Bh[NT*PD];        // (c.W) hi [nt][pd]
__device__ __half g_Bl[NT*PD];
__device__ __half g_vh[NT*BATCH];     // v hi [nt][b]
__device__ __half g_vl[NT*BATCH];
__device__ float  g_spart[KCH1*BATCH*NT];
__device__ float  g_bbar[P*NCAPS];
__device__ float  g_b[P*NCAPS];
__device__ float  g_c[P*NCAPS];

// ---------------- PTX helpers ------------------------------------------------
__device__ __forceinline__ void mma16816(float* c,
    uint32_t a0, uint32_t a1, uint32_t a2, uint32_t a3,
    uint32_t b0, uint32_t b1) {
    asm volatile(
        "mma.sync.aligned.m16n8k16.row.col.f32.f16.f16.f32 "
        "{%0,%1,%2,%3}, {%4,%5,%6,%7}, {%8,%9}, {%0,%1,%2,%3};"
        : "+f"(c[0]), "+f"(c[1]), "+f"(c[2]), "+f"(c[3])
        : "r"(a0), "r"(a1), "r"(a2), "r"(a3), "r"(b0), "r"(b1));
}
__device__ __forceinline__ void ldmx4(uint32_t* r, uint32_t addr) {
    asm volatile("ldmatrix.sync.aligned.m8n8.x4.shared.b16 {%0,%1,%2,%3}, [%4];"
        : "=r"(r[0]), "=r"(r[1]), "=r"(r[2]), "=r"(r[3]) : "r"(addr));
}
__device__ __forceinline__ void ldmx2(uint32_t* r, uint32_t addr) {
    asm volatile("ldmatrix.sync.aligned.m8n8.x2.shared.b16 {%0,%1}, [%2];"
        : "=r"(r[0]), "=r"(r[1]) : "r"(addr));
}
__device__ __forceinline__ uint32_t s2u(const void* p) {
    uint32_t a;
    asm("{ .reg .u64 t; cvta.to.shared.u64 t, %1; cvt.u32.u64 %0, t; }"
        : "=r"(a) : "l"(p));
    return a;
}
__device__ __forceinline__ void cpasync16(uint32_t dst, const void* src) {
    asm volatile("cp.async.cg.shared.global [%0], [%1], 16;"
        :: "r"(dst), "l"(__cvta_generic_to_global(src)));
}
#define CP_COMMIT() asm volatile("cp.async.commit_group;" ::: "memory")
#define CP_WAIT(n)  asm volatile("cp.async.wait_group %0;" :: "n"(n) : "memory")

__device__ __forceinline__ void split2(float v, __half& h, __half& l) {
    h = __float2half_rn(v);
    l = __float2half_rn(v - __half2float(h));
}

// ---------------- prep: W layouts + iter-0 B split + b/c init ----------------
__global__ void k_prep(const float* __restrict__ W) {
    int i = blockIdx.x * blockDim.x + threadIdx.x;
    if (i < NT*PD) {
        int nt = i / PD, pd = i - nt*PD;
        int p = pd >> 3, d = pd & 7, n = nt >> 4, t = nt & 15;
        float w = W[((p*NCAPS + n)*T + t)*D + d];
        g_Wt[i] = w;
        g_Wt2[(size_t)pd*NT + nt] = w;
        __half h, l;
        split2(0.1f * w, h, l);      // iter-0 coupling c = 1/NCAPS
        g_Bh[i] = h; g_Bl[i] = l;
    }
    if (i < P*NCAPS) { g_b[i] = 0.0f; g_c[i] = 0.1f; }
}

// ---------------- prep: split X hi/lo in both layouts ------------------------
__global__ void k_prepX(const float* __restrict__ X) {
    __shared__ uint32_t tb[32][33];
    int pd0 = blockIdx.x * 32, b0 = blockIdx.y * 32;
    int tx = threadIdx.x & 31, ty = threadIdx.x >> 5;
    #pragma unroll
    for (int j = 0; j < 32; j += 8) {
        float v = X[(size_t)(b0 + ty + j)*PD + pd0 + tx];
        __half h, l; split2(v, h, l);
        g_Xh[(size_t)(b0 + ty + j)*PD + pd0 + tx] = h;
        g_Xl[(size_t)(b0 + ty + j)*PD + pd0 + tx] = l;
        __half2 hl = __halves2half2(h, l);
        tb[ty + j][tx] = *(uint32_t*)&hl;
    }
    __syncthreads();
    #pragma unroll
    for (int j = 0; j < 32; j += 8) {
        uint32_t u = tb[tx][ty + j];
        __half2 hl = *(__half2*)&u;
        g_Xth[(size_t)(pd0 + ty + j)*BATCH + b0 + tx] = __low2half(hl);
        g_Xtl[(size_t)(pd0 + ty + j)*BATCH + b0 + tx] = __high2half(hl);
    }
}

// ---------------- per-iter (it>=1): B = split(c .* Wt) -----------------------
__global__ void k_splitB() {
    int i4 = blockIdx.x * blockDim.x + threadIdx.x;
    if (i4 >= NT*PD/4) return;
    size_t base = (size_t)i4 * 4;
    int nt = (int)(base / PD), pd = (int)(base - (size_t)nt*PD);
    float c = g_c[(pd >> 3)*NCAPS + (nt >> 4)];
    float4 w = *(const float4*)&g_Wt[base];
    __half hx, lx, hy, ly, hz, lz, hw, lw;
    split2(w.x*c, hx, lx); split2(w.y*c, hy, ly);
    split2(w.z*c, hz, lz); split2(w.w*c, hw, lw);
    *(__half2*)&g_Bh[base]     = __halves2half2(hx, hy);
    *(__half2*)&g_Bh[base + 2] = __halves2half2(hz, hw);
    *(__half2*)&g_Bl[base]     = __halves2half2(lx, ly);
    *(__half2*)&g_Bl[base + 2] = __halves2half2(lz, lw);
}

// ---------------- SMEM offsets ----------------------------------------------
#define O_AHI(buf) ((buf)*BUF_BYTES)
#define O_ALO(buf) ((buf)*BUF_BYTES + ABYTES)
#define O_BHI(buf) ((buf)*BUF_BYTES + 2*ABYTES)
#define O_BLO(buf) ((buf)*BUF_BYTES + 2*ABYTES + BBYTES)

// compute one K=32 stage; warp tile 32(M) x 40(N); 16-warp grid 4x4
__device__ __forceinline__ void compute_stage(
    uint32_t sb, int buf, int wm32, int wn40, int lane, float acc[2][5][4]) {
    int grpA = lane >> 3, rowA = lane & 7;       // x4: grp 0..3
    int halfB = (lane >> 3) & 1, rowB = lane & 7; // x2: lanes 0-15 meaningful
    #pragma unroll
    for (int ko = 0; ko < 32; ko += 16) {
        uint32_t bh[5][2], bl[5][2];
        #pragma unroll
        for (int bt = 0; bt < 5; ++bt) {
            uint32_t ba = (uint32_t)((wn40 + bt*8 + rowB)*80 + (ko + halfB*8)*2);
            ldmx2(bh[bt], sb + O_BHI(buf) + ba);
            ldmx2(bl[bt], sb + O_BLO(buf) + ba);
        }
        #pragma unroll
        for (int mt = 0; mt < 2; ++mt) {
            uint32_t aa = (uint32_t)((wm32 + mt*16 + (grpA & 1)*8 + rowA)*80
                                     + (ko + (grpA >> 1)*8)*2);
            uint32_t ah[4], al[4];
            ldmx4(ah, sb + O_AHI(buf) + aa);
            ldmx4(al, sb + O_ALO(buf) + aa);
            #pragma unroll
            for (int bt = 0; bt < 5; ++bt) {
                mma16816(acc[mt][bt], ah[0], ah[1], ah[2], ah[3], bh[bt][0], bh[bt][1]);
                mma16816(acc[mt][bt], ah[0], ah[1], ah[2], ah[3], bl[bt][0], bl[bt][1]);
                mma16816(acc[mt][bt], al[0], al[1], al[2], al[3], bh[bt][0], bh[bt][1]);
            }
        }
    }
}

// ---------------- GEMM1 ------------------------------------------------------
__global__ void __launch_bounds__(512) k_gemm1() {
    extern __shared__ char smem[];
    uint32_t sb = s2u(smem);
    int tid = threadIdx.x;
    int wid = tid >> 5, lane = tid & 31;
    int wm32 = (wid >> 2) * 32;
    int wn40 = (wid & 3) * 40;
    int b0 = blockIdx.x * 128;
    int kc = blockIdx.y * 256;

    float acc[2][5][4];
    #pragma unroll
    for (int i = 0; i < 2; ++i)
        #pragma unroll
        for (int j = 0; j < 5; ++j)
            #pragma unroll
            for (int r = 0; r < 4; ++r) acc[i][j][r] = 0.0f;

    auto issue = [&](int s, int buf) {
        int kb = kc + s*32;
        {   // A: 128 rows x 4 chunks = 512 -> 1/thread
            int row = tid >> 2, q = tid & 3;
            cpasync16(sb + O_AHI(buf) + row*80 + q*16,
                      g_Xh + (size_t)(b0 + row)*PD + kb + q*8);
            cpasync16(sb + O_ALO(buf) + row*80 + q*16,
                      g_Xl + (size_t)(b0 + row)*PD + kb + q*8);
        }
        #pragma unroll
        for (int u = 0; u < 2; ++u) {   // B: 160 rows x 4 = 640
            int ch = tid + 512*u;
            if (ch < 640) {
                int row = ch >> 2, q = ch & 3;
                cpasync16(sb + O_BHI(buf) + row*80 + q*16,
                          g_Bh + (size_t)row*PD + kb + q*8);
                cpasync16(sb + O_BLO(buf) + row*80 + q*16,
                          g_Bl + (size_t)row*PD + kb + q*8);
            }
        }
    };

    issue(0, 0); CP_COMMIT();
    issue(1, 1); CP_COMMIT();
    #pragma unroll 1
    for (int s = 0; s < 8; ++s) {
        CP_WAIT(1);
        __syncthreads();
        if (s + 2 < 8) issue(s + 2, (s + 2) % NSTAGE);
        CP_COMMIT();
        compute_stage(sb, s % NSTAGE, wm32, wn40, lane, acc);
    }

    int g = lane >> 2, qq = (lane & 3)*2;
    float* out = g_spart + (size_t)blockIdx.y * BATCH * NT;
    #pragma unroll
    for (int mt = 0; mt < 2; ++mt) {
        int row = b0 + wm32 + mt*16 + g;
        #pragma unroll
        for (int bt = 0; bt < 5; ++bt) {
            int col = wn40 + bt*8 + qq;
            *(float2*)&out[(size_t)row*NT + col]       = make_float2(acc[mt][bt][0], acc[mt][bt][1]);
            *(float2*)&out[(size_t)(row + 8)*NT + col] = make_float2(acc[mt][bt][2], acc[mt][bt][3]);
        }
    }
}

// ---------------- GEMM2 + fused agreement epilogue ---------------------------
__global__ void __launch_bounds__(512) k_gemm2() {
    extern __shared__ char smem[];
    __shared__ float bb[16][12];
    uint32_t sb = s2u(smem);
    int tid = threadIdx.x;
    int wid = tid >> 5, lane = tid & 31;
    int wm32 = (wid >> 2) * 32;
    int wn40 = (wid & 3) * 40;
    int pd0 = blockIdx.x * 128;
    int kc = blockIdx.y * 256;

    if (tid < 160) bb[tid / 10][tid % 10] = 0.0f;

    float acc[2][5][4];
    #pragma unroll
    for (int i = 0; i < 2; ++i)
        #pragma unroll
        for (int j = 0; j < 5; ++j)
            #pragma unroll
            for (int r = 0; r < 4; ++r) acc[i][j][r] = 0.0f;

    auto issue = [&](int s, int buf) {
        int kb = kc + s*32;
        {
            int row = tid >> 2, q = tid & 3;
            cpasync16(sb + O_AHI(buf) + row*80 + q*16,
                      g_Xth + (size_t)(pd0 + row)*BATCH + kb + q*8);
            cpasync16(sb + O_ALO(buf) + row*80 + q*16,
                      g_Xtl + (size_t)(pd0 + row)*BATCH + kb + q*8);
        }
        #pragma unroll
        for (int u = 0; u < 2; ++u) {
            int ch = tid + 512*u;
            if (ch < 640) {
                int row = ch >> 2, q = ch & 3;
                cpasync16(sb + O_BHI(buf) + row*80 + q*16,
                          g_vh + (size_t)row*BATCH + kb + q*8);
                cpasync16(sb + O_BLO(buf) + row*80 + q*16,
                          g_vl + (size_t)row*BATCH + kb + q*8);
            }
        }
    };

    issue(0, 0); CP_COMMIT();
    issue(1, 1); CP_COMMIT();
    #pragma unroll 1
    for (int s = 0; s < 8; ++s) {
        CP_WAIT(1);
        __syncthreads();
        if (s + 2 < 8) issue(s + 2, (s + 2) % NSTAGE);
        CP_COMMIT();
        compute_stage(sb, s % NSTAGE, wm32, wn40, lane, acc);
    }

    int g = lane >> 2, qq = (lane & 3)*2;
    // fused agreement: bbar[p][n] += W (.) acc, reduced over d and t
    #pragma unroll
    for (int mt = 0; mt < 2; ++mt) {
        int r0 = wm32 + mt*16 + g;
        int p0 = (wm32 + mt*16) >> 3;
        #pragma unroll
        for (int bt = 0; bt < 5; ++bt) {
            int col = wn40 + bt*8 + qq;
            int n = col >> 4;
            float2 w0 = *(const float2*)&g_Wt2[(size_t)(pd0 + r0)*NT + col];
            float2 w1 = *(const float2*)&g_Wt2[(size_t)(pd0 + r0 + 8)*NT + col];
            float v0 = acc[mt][bt][0]*w0.x + acc[mt][bt][1]*w0.y;
            float v1 = acc[mt][bt][2]*w1.x + acc[mt][bt][3]*w1.y;
            #pragma unroll
            for (int o = 4; o < 32; o <<= 1) {
                v0 += __shfl_xor_sync(0xffffffffu, v0, o);
                v1 += __shfl_xor_sync(0xffffffffu, v1, o);
            }
            if (lane < 4) {
                atomicAdd(&bb[p0][n], v0);
                atomicAdd(&bb[p0 + 1][n], v1);
            }
        }
    }
    __syncthreads();
    if (tid < 160) {
        const float inv = 1.0f / (float)BATCH;
        atomicAdd(&g_bbar[(pd0/8 + tid/10)*NCAPS + tid % 10],
                  bb[tid / 10][tid % 10] * inv);
    }
}

// ---------------- fused reduce + squash (+ v split + bbar zero) --------------
__global__ void k_redsquash(float* __restrict__ out, int final_it) {
    int i = blockIdx.x * blockDim.x + threadIdx.x;   // [0, BATCH*NT)
    float s = 0.0f;
    #pragma unroll
    for (int ch = 0; ch < KCH1; ++ch)
        s += g_spart[(size_t)ch*BATCH*NT + i];
    float ss = s*s;
    #pragma unroll
    for (int o = 1; o < 16; o <<= 1)
        ss += __shfl_xor_sync(0xffffffffu, ss, o);
    float nrm = sqrtf(ss);
    float f = ss / (1.0f + ss*(nrm + 1e-9f));
    float v = f*s;
    if (final_it) {
        out[i] = v;
    } else {
        int b = i / NT, nt = i - b*NT;
        __half h, l; split2(v, h, l);
        g_vh[(size_t)nt*BATCH + b] = h;
        g_vl[(size_t)nt*BATCH + b] = l;
        if (i < P*NCAPS) g_bbar[i] = 0.0f;
    }
}

// ---------------- routing softmax --------------------------------------------
__global__ void k_route() {
    int p = blockIdx.x * blockDim.x + threadIdx.x;
    if (p >= P) return;
    float bn[NCAPS];
    float mx = -1e30f;
    #pragma unroll
    for (int n = 0; n < NCAPS; ++n) {
        bn[n] = g_b[p*NCAPS + n] + g_bbar[p*NCAPS + n];
        g_b[p*NCAPS + n] = bn[n];
        mx = fmaxf(mx, bn[n]);
    }
    float sum = 0.0f;
    #pragma unroll
    for (int n = 0; n < NCAPS; ++n) { bn[n] = expf(bn[n] - mx); sum += bn[n]; }
    float rs = 1.0f / sum;
    #pragma unroll
    for (int n = 0; n < NCAPS; ++n) g_c[p*NCAPS + n] = bn[n]*rs;
}

// ---------------- launch -----------------------------------------------------
extern "C" void kernel_launch(void* const* d_in, const int* in_sizes, int n_in,
                              void* d_out, int out_size) {
    (void)in_sizes; (void)n_in; (void)out_size;
    const float* x = (const float*)d_in[0];   // [512, 1152, 8]
    const float* W = (const float*)d_in[1];   // [1152, 10, 16, 8]
    float* out = (float*)d_out;               // [512, 10, 16, 1]

    cudaFuncSetAttribute((const void*)k_gemm1,
                         cudaFuncAttributeMaxDynamicSharedMemorySize, SMEM_BYTES);
    cudaFuncSetAttribute((const void*)k_gemm2,
                         cudaFuncAttributeMaxDynamicSharedMemorySize, SMEM_BYTES);

    k_prep<<<(NT*PD + 255)/256, 256>>>(W);
    k_prepX<<<dim3(PD/32, BATCH/32), 256>>>(x);

    for (int it = 0; it < 3; ++it) {
        if (it > 0) k_splitB<<<(NT*PD/4 + 255)/256, 256>>>();
        k_gemm1<<<dim3(BATCH/128, KCH1), 512, SMEM_BYTES>>>();
        k_redsquash<<<(BATCH*NT)/256, 256>>>(out, it == 2 ? 1 : 0);
        if (it < 2) {
            k_gemm2<<<dim3(PD/128, KCH2), 512, SMEM_BYTES>>>();
            k_route<<<(P + 255)/256, 256>>>();
        }
    }
}

// round 6
// speedup vs baseline: 2.3737x; 1.0546x over previous
#include <cuda_runtime.h>
#include <cuda_fp16.h>
#include <math.h>
#include <stdint.h>

#define BATCH 512
#define P 1152
#define NCAPS 10
#define T 16
#define D 8
#define PD 9216          // P*D
#define NT 160           // NCAPS*T
#define KCH1 36          // split-K chunks gemm1 (36*256 = 9216)
#define KCH2 2           // split-K chunks gemm2 (2*256 = 512)

// SMEM stage: K=64 halves (128B) + 16B pad -> 144B row stride (9x16B; banks shift 4/row)
#define SROW 144
#define AOFF_LO 18432            // 128*144
#define BOFF    36864            // A hi+lo
#define BOFF_LO 59904            // +160*144
#define BUF_BYTES 82944          // 2*18432 + 2*23040
#define SMEM_BYTES (2*BUF_BYTES) // 165888

// ---------------- scratch ----------------------------------------------------
__device__ float  g_Wt[NT*PD];        // Wt[nt][pd] fp32
__device__ float  g_Wt2[PD*NT];       // Wt2[pd][nt] fp32 (gemm2 epilogue)
__device__ __half g_Xh[BATCH*PD];     // X hi [b][pd]
__device__ __half g_Xl[BATCH*PD];
__device__ __half g_Xth[PD*BATCH];    // X^T hi [pd][b]
__device__ __half g_Xtl[PD*BATCH];
__device__ __half g_Bh[NT*PD];        // (c.W) hi [nt][pd]
__device__ __half g_Bl[NT*PD];
__device__ __half g_vh[NT*BATCH];     // v hi [nt][b]
__device__ __half g_vl[NT*BATCH];
__device__ float  g_spart[KCH1*BATCH*NT];
__device__ float  g_bbar[P*NCAPS];
__device__ float  g_b[P*NCAPS];

// ---------------- PTX helpers ------------------------------------------------
__device__ __forceinline__ void mma16816(float* c,
    uint32_t a0, uint32_t a1, uint32_t a2, uint32_t a3,
    uint32_t b0, uint32_t b1) {
    asm volatile(
        "mma.sync.aligned.m16n8k16.row.col.f32.f16.f16.f32 "
        "{%0,%1,%2,%3}, {%4,%5,%6,%7}, {%8,%9}, {%0,%1,%2,%3};"
        : "+f"(c[0]), "+f"(c[1]), "+f"(c[2]), "+f"(c[3])
        : "r"(a0), "r"(a1), "r"(a2), "r"(a3), "r"(b0), "r"(b1));
}
__device__ __forceinline__ void ldmx4(uint32_t* r, uint32_t addr) {
    asm volatile("ldmatrix.sync.aligned.m8n8.x4.shared.b16 {%0,%1,%2,%3}, [%4];"
        : "=r"(r[0]), "=r"(r[1]), "=r"(r[2]), "=r"(r[3]) : "r"(addr));
}
__device__ __forceinline__ void ldmx2(uint32_t* r, uint32_t addr) {
    asm volatile("ldmatrix.sync.aligned.m8n8.x2.shared.b16 {%0,%1}, [%2];"
        : "=r"(r[0]), "=r"(r[1]) : "r"(addr));
}
__device__ __forceinline__ uint32_t s2u(const void* p) {
    uint32_t a;
    asm("{ .reg .u64 t; cvta.to.shared.u64 t, %1; cvt.u32.u64 %0, t; }"
        : "=r"(a) : "l"(p));
    return a;
}
__device__ __forceinline__ void cpasync16(uint32_t dst, const void* src) {
    asm volatile("cp.async.cg.shared.global [%0], [%1], 16;"
        :: "r"(dst), "l"(__cvta_generic_to_global(src)));
}
#define CP_COMMIT() asm volatile("cp.async.commit_group;" ::: "memory")
#define CP_WAIT(n)  asm volatile("cp.async.wait_group %0;" :: "n"(n) : "memory")

__device__ __forceinline__ void split2(float v, __half& h, __half& l) {
    h = __float2half_rn(v);
    l = __float2half_rn(v - __half2float(h));
}

// ---------------- fused prep: W layouts, iter-0 B, X splits, zero-init -------
#define PREP_WBLOCKS 5760   // NT*PD/256
#define PREP_XBLOCKS 4608   // (PD/32)*(BATCH/32)
__global__ void k_prepall(const float* __restrict__ W, const float* __restrict__ X) {
    if (blockIdx.x < PREP_WBLOCKS) {
        int i = blockIdx.x * 256 + threadIdx.x;
        int nt = i / PD, pd = i - nt*PD;
        int p = pd >> 3, d = pd & 7, n = nt >> 4, t = nt & 15;
        float w = W[((p*NCAPS + n)*T + t)*D + d];
        g_Wt[i] = w;
        g_Wt2[(size_t)pd*NT + nt] = w;
        __half h, l;
        split2(0.1f * w, h, l);     // iter-0 coupling c = 1/NCAPS
        g_Bh[i] = h; g_Bl[i] = l;
        if (i < P*NCAPS) g_b[i] = 0.0f;
    } else {
        __shared__ uint32_t tb[32][33];
        int bid = blockIdx.x - PREP_WBLOCKS;
        int pd0 = (bid % (PD/32)) * 32, b0 = (bid / (PD/32)) * 32;
        int tx = threadIdx.x & 31, ty = threadIdx.x >> 5;
        #pragma unroll
        for (int j = 0; j < 32; j += 8) {
            float v = X[(size_t)(b0 + ty + j)*PD + pd0 + tx];
            __half h, l; split2(v, h, l);
            g_Xh[(size_t)(b0 + ty + j)*PD + pd0 + tx] = h;
            g_Xl[(size_t)(b0 + ty + j)*PD + pd0 + tx] = l;
            __half2 hl = __halves2half2(h, l);
            tb[ty + j][tx] = *(uint32_t*)&hl;
        }
        __syncthreads();
        #pragma unroll
        for (int j = 0; j < 32; j += 8) {
            uint32_t u = tb[tx][ty + j];
            __half2 hl = *(__half2*)&u;
            g_Xth[(size_t)(pd0 + ty + j)*BATCH + b0 + tx] = __low2half(hl);
            g_Xtl[(size_t)(pd0 + ty + j)*BATCH + b0 + tx] = __high2half(hl);
        }
    }
}

// ---------------- compute one K=64 stage -------------------------------------
// warp tile 32(M) x 40(N), 16 warps as 4x4
__device__ __forceinline__ void compute_stage64(
    uint32_t aHi, uint32_t aLo, uint32_t bHi, uint32_t bLo,
    int wm32, int wn40, int lane, float acc[2][5][4]) {
    int grp = lane >> 3, lr = lane & 7;
    #pragma unroll
    for (int ko = 0; ko < 64; ko += 16) {
        uint32_t bh[5][2], bl[5][2];
        #pragma unroll
        for (int bp = 0; bp < 2; ++bp) {
            uint32_t ba = (uint32_t)((wn40 + bp*16 + ((grp & 2) << 2) + lr)*SROW
                                     + (ko + (grp & 1)*8)*2);
            uint32_t r4[4];
            ldmx4(r4, bHi + ba);
            bh[bp*2][0] = r4[0]; bh[bp*2][1] = r4[1];
            bh[bp*2+1][0] = r4[2]; bh[bp*2+1][1] = r4[3];
            ldmx4(r4, bLo + ba);
            bl[bp*2][0] = r4[0]; bl[bp*2][1] = r4[1];
            bl[bp*2+1][0] = r4[2]; bl[bp*2+1][1] = r4[3];
        }
        {
            uint32_t ba = (uint32_t)((wn40 + 32 + lr)*SROW + (ko + grp*8)*2);
            ldmx2(bh[4], bHi + ba);
            ldmx2(bl[4], bLo + ba);
        }
        #pragma unroll
        for (int mt = 0; mt < 2; ++mt) {
            uint32_t aa = (uint32_t)((wm32 + mt*16 + (grp & 1)*8 + lr)*SROW
                                     + (ko + (grp >> 1)*8)*2);
            uint32_t ah[4], al[4];
            ldmx4(ah, aHi + aa);
            ldmx4(al, aLo + aa);
            #pragma unroll
            for (int bt = 0; bt < 5; ++bt) {
                mma16816(acc[mt][bt], ah[0], ah[1], ah[2], ah[3], bh[bt][0], bh[bt][1]);
                mma16816(acc[mt][bt], ah[0], ah[1], ah[2], ah[3], bl[bt][0], bl[bt][1]);
                mma16816(acc[mt][bt], al[0], al[1], al[2], al[3], bh[bt][0], bh[bt][1]);
            }
        }
    }
}

// ---------------- GEMM1: spart[ch] = Xsplit[128b x 256k] (c.W)split[256k x 160]
__global__ void __launch_bounds__(512) k_gemm1() {
    extern __shared__ char smem[];
    uint32_t sb = s2u(smem);
    int tid = threadIdx.x;
    int wid = tid >> 5, lane = tid & 31;
    int wm32 = (wid >> 2) * 32;
    int wn40 = (wid & 3) * 40;
    int b0 = blockIdx.x * 128;
    int kc = blockIdx.y * 256;

    float acc[2][5][4];
    #pragma unroll
    for (int i = 0; i < 2; ++i)
        #pragma unroll
        for (int j = 0; j < 5; ++j)
            #pragma unroll
            for (int r = 0; r < 4; ++r) acc[i][j][r] = 0.0f;

    auto issue = [&](int s, int buf) {
        int kb = kc + s*64;
        uint32_t base = sb + buf*BUF_BYTES;
        #pragma unroll
        for (int u = 0; u < 2; ++u) {    // A: 128 rows x 8 chunks = 1024
            int ch = tid*2 + u, row = ch >> 3, q = ch & 7;
            cpasync16(base + row*SROW + q*16,
                      g_Xh + (size_t)(b0 + row)*PD + kb + q*8);
            cpasync16(base + AOFF_LO + row*SROW + q*16,
                      g_Xl + (size_t)(b0 + row)*PD + kb + q*8);
        }
        #pragma unroll
        for (int u = 0; u < 3; ++u) {    // B: 160 rows x 8 = 1280
            int ch = tid + 512*u;
            if (ch < 1280) {
                int row = ch >> 3, q = ch & 7;
                cpasync16(base + BOFF + row*SROW + q*16,
                          g_Bh + (size_t)row*PD + kb + q*8);
                cpasync16(base + BOFF_LO + row*SROW + q*16,
                          g_Bl + (size_t)row*PD + kb + q*8);
            }
        }
    };

    issue(0, 0); CP_COMMIT();
    #pragma unroll 1
    for (int s = 0; s < 4; ++s) {
        CP_WAIT(0);
        __syncthreads();
        if (s < 3) { issue(s + 1, (s + 1) & 1); CP_COMMIT(); }
        uint32_t base = sb + (s & 1)*BUF_BYTES;
        compute_stage64(base, base + AOFF_LO, base + BOFF, base + BOFF_LO,
                        wm32, wn40, lane, acc);
    }

    int g = lane >> 2, qq = (lane & 3)*2;
    float* out = g_spart + (size_t)blockIdx.y * BATCH * NT;
    #pragma unroll
    for (int mt = 0; mt < 2; ++mt) {
        int row = b0 + wm32 + mt*16 + g;
        #pragma unroll
        for (int bt = 0; bt < 5; ++bt) {
            int col = wn40 + bt*8 + qq;
            *(float2*)&out[(size_t)row*NT + col]       = make_float2(acc[mt][bt][0], acc[mt][bt][1]);
            *(float2*)&out[(size_t)(row + 8)*NT + col] = make_float2(acc[mt][bt][2], acc[mt][bt][3]);
        }
    }
}

// ---------------- GEMM2 + fused agreement epilogue ---------------------------
__global__ void __launch_bounds__(512) k_gemm2() {
    extern __shared__ char smem[];
    __shared__ float bb[16][12];
    uint32_t sb = s2u(smem);
    int tid = threadIdx.x;
    int wid = tid >> 5, lane = tid & 31;
    int wm32 = (wid >> 2) * 32;
    int wn40 = (wid & 3) * 40;
    int pd0 = blockIdx.x * 128;
    int kc = blockIdx.y * 256;

    if (tid < 160) bb[tid / 10][tid % 10] = 0.0f;

    float acc[2][5][4];
    #pragma unroll
    for (int i = 0; i < 2; ++i)
        #pragma unroll
        for (int j = 0; j < 5; ++j)
            #pragma unroll
            for (int r = 0; r < 4; ++r) acc[i][j][r] = 0.0f;

    auto issue = [&](int s, int buf) {
        int kb = kc + s*64;
        uint32_t base = sb + buf*BUF_BYTES;
        #pragma unroll
        for (int u = 0; u < 2; ++u) {
            int ch = tid*2 + u, row = ch >> 3, q = ch & 7;
            cpasync16(base + row*SROW + q*16,
                      g_Xth + (size_t)(pd0 + row)*BATCH + kb + q*8);
            cpasync16(base + AOFF_LO + row*SROW + q*16,
                      g_Xtl + (size_t)(pd0 + row)*BATCH + kb + q*8);
        }
        #pragma unroll
        for (int u = 0; u < 3; ++u) {
            int ch = tid + 512*u;
            if (ch < 1280) {
                int row = ch >> 3, q = ch & 7;
                cpasync16(base + BOFF + row*SROW + q*16,
                          g_vh + (size_t)row*BATCH + kb + q*8);
                cpasync16(base + BOFF_LO + row*SROW + q*16,
                          g_vl + (size_t)row*BATCH + kb + q*8);
            }
        }
    };

    issue(0, 0); CP_COMMIT();
    #pragma unroll 1
    for (int s = 0; s < 4; ++s) {
        CP_WAIT(0);
        __syncthreads();
        if (s < 3) { issue(s + 1, (s + 1) & 1); CP_COMMIT(); }
        uint32_t base = sb + (s & 1)*BUF_BYTES;
        compute_stage64(base, base + AOFF_LO, base + BOFF, base + BOFF_LO,
                        wm32, wn40, lane, acc);
    }

    int g = lane >> 2, qq = (lane & 3)*2;
    #pragma unroll
    for (int mt = 0; mt < 2; ++mt) {
        int r0 = wm32 + mt*16 + g;
        int p0 = (wm32 + mt*16) >> 3;
        #pragma unroll
        for (int bt = 0; bt < 5; ++bt) {
            int col = wn40 + bt*8 + qq;
            int n = col >> 4;
            float2 w0 = *(const float2*)&g_Wt2[(size_t)(pd0 + r0)*NT + col];
            float2 w1 = *(const float2*)&g_Wt2[(size_t)(pd0 + r0 + 8)*NT + col];
            float v0 = acc[mt][bt][0]*w0.x + acc[mt][bt][1]*w0.y;
            float v1 = acc[mt][bt][2]*w1.x + acc[mt][bt][3]*w1.y;
            #pragma unroll
            for (int o = 4; o < 32; o <<= 1) {
                v0 += __shfl_xor_sync(0xffffffffu, v0, o);
                v1 += __shfl_xor_sync(0xffffffffu, v1, o);
            }
            if (lane < 4) {
                atomicAdd(&bb[p0][n], v0);
                atomicAdd(&bb[p0 + 1][n], v1);
            }
        }
    }
    __syncthreads();
    if (tid < 160) {
        const float inv = 1.0f / (float)BATCH;
        atomicAdd(&g_bbar[(pd0/8 + tid/10)*NCAPS + tid % 10],
                  bb[tid / 10][tid % 10] * inv);
    }
}

// ---------------- fused reduce + squash (float2; zero bbar) ------------------
__global__ void k_redsquash(float* __restrict__ out, int final_it) {
    int i2 = blockIdx.x * blockDim.x + threadIdx.x;   // [0, BATCH*NT/2)
    const float2* sp = (const float2*)g_spart;
    float2 s = make_float2(0.0f, 0.0f);
    #pragma unroll
    for (int ch = 0; ch < KCH1; ++ch) {
        float2 t = sp[(size_t)ch*(BATCH*NT/2) + i2];
        s.x += t.x; s.y += t.y;
    }
    float ss = s.x*s.x + s.y*s.y;
    #pragma unroll
    for (int o = 1; o < 8; o <<= 1)
        ss += __shfl_xor_sync(0xffffffffu, ss, o);    // 8 lanes x 2 = 16 t's
    float nrm = sqrtf(ss);
    float f = ss / (1.0f + ss*(nrm + 1e-9f));
    float v0 = f*s.x, v1 = f*s.y;
    if (final_it) {
        *(float2*)&out[2*i2] = make_float2(v0, v1);
    } else {
        int idx = 2*i2;
        int b = idx / NT, nt = idx - b*NT;
        __half h, l;
        split2(v0, h, l);
        g_vh[(size_t)nt*BATCH + b] = h;  g_vl[(size_t)nt*BATCH + b] = l;
        split2(v1, h, l);
        g_vh[(size_t)(nt+1)*BATCH + b] = h;  g_vl[(size_t)(nt+1)*BATCH + b] = l;
        if (i2 < P*NCAPS/2) {
            g_bbar[2*i2] = 0.0f; g_bbar[2*i2 + 1] = 0.0f;
        }
    }
}

// ---------------- fused route (softmax) + splitB -----------------------------
// 144 blocks x 256 threads; block owns pd range [blk*64, blk*64+64) = 8 p's
__global__ void __launch_bounds__(256) k_routesplitB() {
    __shared__ float sbn[8][10];
    __shared__ float sc[8][10];
    int tid = threadIdx.x;
    int p0 = blockIdx.x * 8;
    int pd0 = blockIdx.x * 64;

    if (tid < 80) {
        int lp = tid / 10, n = tid - lp*10;
        int p = p0 + lp;
        float bn = g_b[p*NCAPS + n] + g_bbar[p*NCAPS + n];
        g_b[p*NCAPS + n] = bn;
        sbn[lp][n] = bn;
    }
    __syncthreads();
    if (tid < 8) {
        float mx = -1e30f;
        #pragma unroll
        for (int n = 0; n < NCAPS; ++n) mx = fmaxf(mx, sbn[tid][n]);
        float sum = 0.0f;
        float e[NCAPS];
        #pragma unroll
        for (int n = 0; n < NCAPS; ++n) { e[n] = expf(sbn[tid][n] - mx); sum += e[n]; }
        float rs = 1.0f / sum;
        #pragma unroll
        for (int n = 0; n < NCAPS; ++n) sc[tid][n] = e[n]*rs;
    }
    __syncthreads();

    #pragma unroll
    for (int u = 0; u < 10; ++u) {
        int fl = tid + 256*u;          // 0..2559: 160 nt x 16 pd-quads
        int nt = fl >> 4, pdq = fl & 15;
        int pd = pd0 + pdq*4;
        float c = sc[pdq >> 1][nt >> 4];
        float4 w = *(const float4*)&g_Wt[(size_t)nt*PD + pd];
        __half hx, lx, hy, ly, hz, lz, hw, lw;
        split2(w.x*c, hx, lx); split2(w.y*c, hy, ly);
        split2(w.z*c, hz, lz); split2(w.w*c, hw, lw);
        size_t base = (size_t)nt*PD + pd;
        *(__half2*)&g_Bh[base]     = __halves2half2(hx, hy);
        *(__half2*)&g_Bh[base + 2] = __halves2half2(hz, hw);
        *(__half2*)&g_Bl[base]     = __halves2half2(lx, ly);
        *(__half2*)&g_Bl[base + 2] = __halves2half2(lz, lw);
    }
}

// ---------------- launch -----------------------------------------------------
extern "C" void kernel_launch(void* const* d_in, const int* in_sizes, int n_in,
                              void* d_out, int out_size) {
    (void)in_sizes; (void)n_in; (void)out_size;
    const float* x = (const float*)d_in[0];   // [512, 1152, 8]
    const float* W = (const float*)d_in[1];   // [1152, 10, 16, 8]
    float* out = (float*)d_out;               // [512, 10, 16, 1]

    cudaFuncSetAttribute((const void*)k_gemm1,
                         cudaFuncAttributeMaxDynamicSharedMemorySize, SMEM_BYTES);
    cudaFuncSetAttribute((const void*)k_gemm2,
                         cudaFuncAttributeMaxDynamicSharedMemorySize, SMEM_BYTES);

    k_prepall<<<PREP_WBLOCKS + PREP_XBLOCKS, 256>>>(W, x);

    for (int it = 0; it < 3; ++it) {
        k_gemm1<<<dim3(BATCH/128, KCH1), 512, SMEM_BYTES>>>();
        k_redsquash<<<(BATCH*NT/2)/256, 256>>>(out, it == 2 ? 1 : 0);
        if (it < 2) {
            k_gemm2<<<dim3(PD/128, KCH2), 512, SMEM_BYTES>>>();
            k_routesplitB<<<P/8, 256>>>();
        }
    }
}